// round 4
// baseline (speedup 1.0000x reference)
#include <cuda_runtime.h>
#include <cstdint>

#define TOKENS 4096
#define DMODEL 1024
#define NEXP   8
#define TOPK   2
#define HID    4096
#define CAP    1024

// ---------------- device scratch (no allocations allowed) ----------------
__device__ int   g_idx[TOKENS * TOPK];
__device__ float g_gate[TOKENS * TOPK];
__device__ int   g_slot_tok[NEXP * CAP];
__device__ float g_slot_w[NEXP * CAP];
__device__ float g_h[(size_t)NEXP * CAP * HID];   // 134 MB expert-hidden scratch

// ---------------- helpers ----------------
__device__ __forceinline__ float tf32r(float x) {
    unsigned u;
    asm("cvt.rna.tf32.f32 %0, %1;" : "=r"(u) : "f"(x));
    return __uint_as_float(u);
}
__device__ __forceinline__ float4 tf32r4(float4 v) {
    v.x = tf32r(v.x); v.y = tf32r(v.y); v.z = tf32r(v.z); v.w = tf32r(v.w);
    return v;
}
__device__ __forceinline__ void mma8(float c[4], const unsigned a[4], const unsigned b[2]) {
    asm volatile(
        "mma.sync.aligned.m16n8k8.row.col.f32.tf32.tf32.f32 "
        "{%0,%1,%2,%3}, {%4,%5,%6,%7}, {%8,%9}, {%0,%1,%2,%3};\n"
        : "+f"(c[0]), "+f"(c[1]), "+f"(c[2]), "+f"(c[3])
        : "r"(a[0]), "r"(a[1]), "r"(a[2]), "r"(a[3]), "r"(b[0]), "r"(b[1]));
}

// ---------------- gating: logits -> top2 -> renormalized gates ----------------
// grid 512 x 256 threads: 1 warp per token. Also zeroes y (poisoned by harness).
__global__ void gating_kernel(const float* __restrict__ x, const float* __restrict__ wg,
                              float* __restrict__ y) {
    // zero output: 4096*1024 floats = 1,048,576 float4 / 131072 threads = 8 each
    int gt = blockIdx.x * blockDim.x + threadIdx.x;
    float4 z4 = make_float4(0.f, 0.f, 0.f, 0.f);
#pragma unroll
    for (int i = 0; i < 8; i++)
        ((float4*)y)[gt + i * 131072] = z4;

    int warp = threadIdx.x >> 5, lane = threadIdx.x & 31;
    int t = blockIdx.x * 8 + warp;
    const float4* xr = (const float4*)(x + (size_t)t * DMODEL);
    float lg[8] = {0.f, 0.f, 0.f, 0.f, 0.f, 0.f, 0.f, 0.f};
#pragma unroll
    for (int j = 0; j < 8; j++) {
        int d4 = lane + 32 * j;                    // float4 index along D
        float4 v = xr[d4];
        const float4* wr = (const float4*)(wg + d4 * 4 * NEXP);
        float xv[4] = {v.x, v.y, v.z, v.w};
#pragma unroll
        for (int r = 0; r < 4; r++) {
            float4 w0 = wr[2 * r], w1v = wr[2 * r + 1];
            lg[0] += xv[r] * w0.x;  lg[1] += xv[r] * w0.y;
            lg[2] += xv[r] * w0.z;  lg[3] += xv[r] * w0.w;
            lg[4] += xv[r] * w1v.x; lg[5] += xv[r] * w1v.y;
            lg[6] += xv[r] * w1v.z; lg[7] += xv[r] * w1v.w;
        }
    }
#pragma unroll
    for (int e = 0; e < 8; e++) {
#pragma unroll
        for (int off = 16; off; off >>= 1)
            lg[e] += __shfl_xor_sync(0xffffffffu, lg[e], off);
    }
    if (lane == 0) {
        int e1 = 0; float l1 = lg[0];
        for (int e = 1; e < 8; e++) if (lg[e] > l1) { l1 = lg[e]; e1 = e; }
        int e2 = (e1 == 0) ? 1 : 0; float l2 = lg[e2];
        for (int e = 0; e < 8; e++) if (e != e1 && lg[e] > l2) { l2 = lg[e]; e2 = e; }
        // softmax top-2 renormalized: g1 = exp(l1)/(exp(l1)+exp(l2))
        float gg = 1.f / (1.f + expf(l2 - l1));
        g_idx[t * 2] = e1;  g_idx[t * 2 + 1] = e2;
        g_gate[t * 2] = gg; g_gate[t * 2 + 1] = 1.f - gg;
    }
}

// ---------------- GShard slot-major assignment scan ----------------
// one block, 1024 threads, 8 entries each (K*T = 8192 slot-major entries)
__global__ void scan_kernel() {
    __shared__ unsigned long long sl[2][1024];
    __shared__ unsigned long long sh[2][1024];
    int tid = threadIdx.x;
    // init slot maps
    for (int i = tid; i < NEXP * CAP; i += 1024) { g_slot_tok[i] = -1; g_slot_w[i] = 0.f; }

    int ev[8];
    unsigned long long lo = 0ull, hi = 0ull;   // 4 x 16-bit counters each
#pragma unroll
    for (int j = 0; j < 8; j++) {
        int i = tid * 8 + j;
        int k = i >> 12;            // slot-major: k outer
        int t = i & 4095;
        int e = g_idx[t * 2 + k];
        ev[j] = e;
        if (e < 4) lo += 1ull << (16 * e); else hi += 1ull << (16 * (e - 4));
    }
    sl[0][tid] = lo; sh[0][tid] = hi;
    __syncthreads();
    int buf = 0;
    for (int off = 1; off < 1024; off <<= 1) {
        unsigned long long nl = sl[buf][tid], nh = sh[buf][tid];
        if (tid >= off) { nl += sl[buf][tid - off]; nh += sh[buf][tid - off]; }
        sl[buf ^ 1][tid] = nl; sh[buf ^ 1][tid] = nh;
        buf ^= 1;
        __syncthreads();
    }
    unsigned long long exl = sl[buf][tid] - lo;   // exclusive prefix
    unsigned long long exh = sh[buf][tid] - hi;
    int base[8];
#pragma unroll
    for (int e = 0; e < 4; e++) base[e]     = (int)((exl >> (16 * e)) & 0xFFFF);
#pragma unroll
    for (int e = 0; e < 4; e++) base[4 + e] = (int)((exh >> (16 * e)) & 0xFFFF);
#pragma unroll
    for (int j = 0; j < 8; j++) {
        int i = tid * 8 + j;
        int k = i >> 12;
        int t = i & 4095;
        int e = ev[j];
        int loc = base[e]++;
        if (loc < CAP) {                         // capacity drop
            g_slot_tok[e * CAP + loc] = t;
            g_slot_w[e * CAP + loc]   = g_gate[t * 2 + k];
        }
    }
}

// ---------------- GEMM1: h = relu(gather(x) @ w1 + b1), tf32 MMA ----------------
// block 128x128, BK=32, 256 thr (8 warps of 64x32). grid (HID/128, CAP/128, E)
__global__ __launch_bounds__(256, 2)
void gemm1_kernel(const float* __restrict__ x, const float* __restrict__ w1,
                  const float* __restrict__ b1) {
    __shared__ float As[128][36];   // ldA=36: bank = 4g+tg, conflict-free
    __shared__ float Bs[32][136];   // ldB=136: bank = 8tg+g, conflict-free
    __shared__ int tokS[128];
    const int e  = blockIdx.z;
    const int m0 = blockIdx.y * 128;
    const int n0 = blockIdx.x * 128;
    const int tid = threadIdx.x;
    if (tid < 128) tokS[tid] = g_slot_tok[e * CAP + m0 + tid];
    __syncthreads();

    const float* w1e = w1 + (size_t)e * DMODEL * HID;
    const int warp = tid >> 5, lane = tid & 31;
    const int wm = (warp >> 2) * 64, wn = (warp & 3) * 32;
    const int g = lane >> 2, tg = lane & 3;

    float acc[4][4][4];
#pragma unroll
    for (int mf = 0; mf < 4; mf++)
#pragma unroll
        for (int nf = 0; nf < 4; nf++)
#pragma unroll
            for (int i = 0; i < 4; i++) acc[mf][nf][i] = 0.f;

    for (int k0 = 0; k0 < DMODEL; k0 += 32) {
        float4 aReg[4], bReg[4];
#pragma unroll
        for (int r = 0; r < 4; r++) {
            int idx = tid + 256 * r;
            int m = idx >> 3, kq = idx & 7;
            int tok = tokS[m];
            aReg[r] = make_float4(0.f, 0.f, 0.f, 0.f);
            if (tok >= 0)
                aReg[r] = *(const float4*)(x + (size_t)tok * DMODEL + k0 + kq * 4);
            int row = idx >> 5, c4 = idx & 31;
            bReg[r] = *(const float4*)(w1e + (size_t)(k0 + row) * HID + n0 + c4 * 4);
        }
        __syncthreads();
#pragma unroll
        for (int r = 0; r < 4; r++) {
            int idx = tid + 256 * r;
            int m = idx >> 3, kq = idx & 7;
            *(float4*)&As[m][kq * 4] = tf32r4(aReg[r]);
            int row = idx >> 5, c4 = idx & 31;
            *(float4*)&Bs[row][c4 * 4] = tf32r4(bReg[r]);
        }
        __syncthreads();
#pragma unroll
        for (int ks = 0; ks < 4; ks++) {
            const int kk = ks * 8;
            unsigned a[4][4], bb[4][2];
#pragma unroll
            for (int mf = 0; mf < 4; mf++) {
                int mr = wm + mf * 16;
                a[mf][0] = __float_as_uint(As[mr + g][kk + tg]);
                a[mf][1] = __float_as_uint(As[mr + g + 8][kk + tg]);
                a[mf][2] = __float_as_uint(As[mr + g][kk + tg + 4]);
                a[mf][3] = __float_as_uint(As[mr + g + 8][kk + tg + 4]);
            }
#pragma unroll
            for (int nf = 0; nf < 4; nf++) {
                int nc = wn + nf * 8 + g;
                bb[nf][0] = __float_as_uint(Bs[kk + tg][nc]);
                bb[nf][1] = __float_as_uint(Bs[kk + tg + 4][nc]);
            }
#pragma unroll
            for (int mf = 0; mf < 4; mf++)
#pragma unroll
                for (int nf = 0; nf < 4; nf++)
                    mma8(acc[mf][nf], a[mf], bb[nf]);
        }
    }

    float* he = g_h + (size_t)e * CAP * HID;
    const float* b1e = b1 + e * HID;
#pragma unroll
    for (int mf = 0; mf < 4; mf++) {
        int r0 = m0 + wm + mf * 16 + g;
#pragma unroll
        for (int nf = 0; nf < 4; nf++) {
            int c0 = n0 + wn + nf * 8 + 2 * tg;
            float bv0 = b1e[c0], bv1 = b1e[c0 + 1];
            float2 v01 = make_float2(fmaxf(acc[mf][nf][0] + bv0, 0.f),
                                     fmaxf(acc[mf][nf][1] + bv1, 0.f));
            float2 v23 = make_float2(fmaxf(acc[mf][nf][2] + bv0, 0.f),
                                     fmaxf(acc[mf][nf][3] + bv1, 0.f));
            *(float2*)(he + (size_t)r0 * HID + c0)       = v01;
            *(float2*)(he + (size_t)(r0 + 8) * HID + c0) = v23;
        }
    }
}

// ---------------- GEMM2: out = h @ w2 + b2, fused gate-weighted combine ----------------
// grid (DMODEL/128, CAP/128, E)
__global__ __launch_bounds__(256, 2)
void gemm2_kernel(const float* __restrict__ w2, const float* __restrict__ b2,
                  float* __restrict__ y) {
    __shared__ float As[128][36];
    __shared__ float Bs[32][136];
    const int e  = blockIdx.z;
    const int m0 = blockIdx.y * 128;
    const int n0 = blockIdx.x * 128;
    const int tid = threadIdx.x;
    const float* he  = g_h + (size_t)e * CAP * HID;
    const float* w2e = w2 + (size_t)e * HID * DMODEL;
    const int warp = tid >> 5, lane = tid & 31;
    const int wm = (warp >> 2) * 64, wn = (warp & 3) * 32;
    const int g = lane >> 2, tg = lane & 3;

    float acc[4][4][4];
#pragma unroll
    for (int mf = 0; mf < 4; mf++)
#pragma unroll
        for (int nf = 0; nf < 4; nf++)
#pragma unroll
            for (int i = 0; i < 4; i++) acc[mf][nf][i] = 0.f;

    for (int k0 = 0; k0 < HID; k0 += 32) {
        float4 aReg[4], bReg[4];
#pragma unroll
        for (int r = 0; r < 4; r++) {
            int idx = tid + 256 * r;
            int m = idx >> 3, kq = idx & 7;
            aReg[r] = *(const float4*)(he + (size_t)(m0 + m) * HID + k0 + kq * 4);
            int row = idx >> 5, c4 = idx & 31;
            bReg[r] = *(const float4*)(w2e + (size_t)(k0 + row) * DMODEL + n0 + c4 * 4);
        }
        __syncthreads();
#pragma unroll
        for (int r = 0; r < 4; r++) {
            int idx = tid + 256 * r;
            int m = idx >> 3, kq = idx & 7;
            *(float4*)&As[m][kq * 4] = tf32r4(aReg[r]);
            int row = idx >> 5, c4 = idx & 31;
            *(float4*)&Bs[row][c4 * 4] = tf32r4(bReg[r]);
        }
        __syncthreads();
#pragma unroll
        for (int ks = 0; ks < 4; ks++) {
            const int kk = ks * 8;
            unsigned a[4][4], bb[4][2];
#pragma unroll
            for (int mf = 0; mf < 4; mf++) {
                int mr = wm + mf * 16;
                a[mf][0] = __float_as_uint(As[mr + g][kk + tg]);
                a[mf][1] = __float_as_uint(As[mr + g + 8][kk + tg]);
                a[mf][2] = __float_as_uint(As[mr + g][kk + tg + 4]);
                a[mf][3] = __float_as_uint(As[mr + g + 8][kk + tg + 4]);
            }
#pragma unroll
            for (int nf = 0; nf < 4; nf++) {
                int nc = wn + nf * 8 + g;
                bb[nf][0] = __float_as_uint(Bs[kk + tg][nc]);
                bb[nf][1] = __float_as_uint(Bs[kk + tg + 4][nc]);
            }
#pragma unroll
            for (int mf = 0; mf < 4; mf++)
#pragma unroll
                for (int nf = 0; nf < 4; nf++)
                    mma8(acc[mf][nf], a[mf], bb[nf]);
        }
    }

    const float* b2e = b2 + e * DMODEL;
#pragma unroll
    for (int mf = 0; mf < 4; mf++) {
        int r0 = m0 + wm + mf * 16 + g;
        int tokA = g_slot_tok[e * CAP + r0];
        float wA = g_slot_w[e * CAP + r0];
        int tokB = g_slot_tok[e * CAP + r0 + 8];
        float wB = g_slot_w[e * CAP + r0 + 8];
#pragma unroll
        for (int nf = 0; nf < 4; nf++) {
            int c0 = n0 + wn + nf * 8 + 2 * tg;
            float bv0 = b2e[c0], bv1 = b2e[c0 + 1];
            if (tokA >= 0) {
                atomicAdd(y + (size_t)tokA * DMODEL + c0,     wA * (acc[mf][nf][0] + bv0));
                atomicAdd(y + (size_t)tokA * DMODEL + c0 + 1, wA * (acc[mf][nf][1] + bv1));
            }
            if (tokB >= 0) {
                atomicAdd(y + (size_t)tokB * DMODEL + c0,     wB * (acc[mf][nf][2] + bv0));
                atomicAdd(y + (size_t)tokB * DMODEL + c0 + 1, wB * (acc[mf][nf][3] + bv1));
            }
        }
    }
}

// ---------------- launcher ----------------
extern "C" void kernel_launch(void* const* d_in, const int* in_sizes, int n_in,
                              void* d_out, int out_size) {
    (void)in_sizes; (void)n_in; (void)out_size;
    const float* x  = (const float*)d_in[0];
    const float* wg = (const float*)d_in[1];
    const float* w1 = (const float*)d_in[2];
    const float* b1 = (const float*)d_in[3];
    const float* w2 = (const float*)d_in[4];
    const float* b2 = (const float*)d_in[5];
    float* y = (float*)d_out;

    gating_kernel<<<TOKENS / 8, 256>>>(x, wg, y);
    scan_kernel<<<1, 1024>>>();
    gemm1_kernel<<<dim3(HID / 128, CAP / 128, NEXP), 256>>>(x, w1, b1);
    gemm2_kernel<<<dim3(DMODEL / 128, CAP / 128, NEXP), 256>>>(w2, b2, y);
}

// round 6
// speedup vs baseline: 1.0533x; 1.0533x over previous
#include <cuda_runtime.h>
#include <cstdint>

#define TOKENS 4096
#define DMODEL 1024
#define NEXP   8
#define TOPK   2
#define HID    4096
#define CAP    1024

// smem tile geometry (floats)
#define AS_LD   36
#define BS_LD   136
#define AS_SZ   (128 * AS_LD)          // 4608
#define BS_SZ   (32 * BS_LD)           // 4352
#define STAGE_F (AS_SZ + BS_SZ)        // 8960 floats per stage
#define SMEM_BYTES (2 * STAGE_F * 4)   // 71680 B, 2 stages

// ---------------- device scratch (no allocations allowed) ----------------
__device__ int   g_idx[TOKENS * TOPK];
__device__ float g_gate[TOKENS * TOPK];
__device__ int   g_slot_tok[NEXP * CAP];
__device__ float g_slot_w[NEXP * CAP];
__device__ float g_h[(size_t)NEXP * CAP * HID];   // 134 MB expert-hidden scratch

// ---------------- helpers ----------------
__device__ __forceinline__ unsigned tf32u(float x) {
    unsigned u;
    asm("cvt.rna.tf32.f32 %0, %1;" : "=r"(u) : "f"(x));
    return u;
}
__device__ __forceinline__ void mma8(float c[4], const unsigned a[4], const unsigned b[2]) {
    asm volatile(
        "mma.sync.aligned.m16n8k8.row.col.f32.tf32.tf32.f32 "
        "{%0,%1,%2,%3}, {%4,%5,%6,%7}, {%8,%9}, {%0,%1,%2,%3};\n"
        : "+f"(c[0]), "+f"(c[1]), "+f"(c[2]), "+f"(c[3])
        : "r"(a[0]), "r"(a[1]), "r"(a[2]), "r"(a[3]), "r"(b[0]), "r"(b[1]));
}
__device__ __forceinline__ void cp16(unsigned saddr, const void* g) {
    asm volatile("cp.async.cg.shared.global [%0], [%1], 16;\n" :: "r"(saddr), "l"(g));
}
__device__ __forceinline__ void cp16z(unsigned saddr, const void* g, unsigned sz) {
    asm volatile("cp.async.cg.shared.global [%0], [%1], 16, %2;\n" :: "r"(saddr), "l"(g), "r"(sz));
}
__device__ __forceinline__ void cp_commit() { asm volatile("cp.async.commit_group;\n"); }

// ---------------- gating: logits -> top2 -> renormalized gates ----------------
// grid 512 x 256 threads: 1 warp per token. Also zeroes y (poisoned by harness).
__global__ void gating_kernel(const float* __restrict__ x, const float* __restrict__ wg,
                              float* __restrict__ y) {
    int gt = blockIdx.x * blockDim.x + threadIdx.x;
    float4 z4 = make_float4(0.f, 0.f, 0.f, 0.f);
#pragma unroll
    for (int i = 0; i < 8; i++)
        ((float4*)y)[gt + i * 131072] = z4;

    int warp = threadIdx.x >> 5, lane = threadIdx.x & 31;
    int t = blockIdx.x * 8 + warp;
    const float4* xr = (const float4*)(x + (size_t)t * DMODEL);
    float lg[8] = {0.f, 0.f, 0.f, 0.f, 0.f, 0.f, 0.f, 0.f};
#pragma unroll
    for (int j = 0; j < 8; j++) {
        int d4 = lane + 32 * j;
        float4 v = xr[d4];
        const float4* wr = (const float4*)(wg + d4 * 4 * NEXP);
        float xv[4] = {v.x, v.y, v.z, v.w};
#pragma unroll
        for (int r = 0; r < 4; r++) {
            float4 w0 = wr[2 * r], w1v = wr[2 * r + 1];
            lg[0] += xv[r] * w0.x;  lg[1] += xv[r] * w0.y;
            lg[2] += xv[r] * w0.z;  lg[3] += xv[r] * w0.w;
            lg[4] += xv[r] * w1v.x; lg[5] += xv[r] * w1v.y;
            lg[6] += xv[r] * w1v.z; lg[7] += xv[r] * w1v.w;
        }
    }
#pragma unroll
    for (int e = 0; e < 8; e++) {
#pragma unroll
        for (int off = 16; off; off >>= 1)
            lg[e] += __shfl_xor_sync(0xffffffffu, lg[e], off);
    }
    if (lane == 0) {
        int e1 = 0; float l1 = lg[0];
        for (int e = 1; e < 8; e++) if (lg[e] > l1) { l1 = lg[e]; e1 = e; }
        int e2 = (e1 == 0) ? 1 : 0; float l2 = lg[e2];
        for (int e = 0; e < 8; e++) if (e != e1 && lg[e] > l2) { l2 = lg[e]; e2 = e; }
        float gg = 1.f / (1.f + expf(l2 - l1));
        g_idx[t * 2] = e1;  g_idx[t * 2 + 1] = e2;
        g_gate[t * 2] = gg; g_gate[t * 2 + 1] = 1.f - gg;
    }
}

// ---------------- GShard slot-major assignment scan ----------------
__global__ void scan_kernel() {
    __shared__ unsigned long long sl[2][1024];
    __shared__ unsigned long long sh[2][1024];
    int tid = threadIdx.x;
    for (int i = tid; i < NEXP * CAP; i += 1024) { g_slot_tok[i] = -1; g_slot_w[i] = 0.f; }

    int ev[8];
    unsigned long long lo = 0ull, hi = 0ull;
#pragma unroll
    for (int j = 0; j < 8; j++) {
        int i = tid * 8 + j;
        int k = i >> 12;
        int t = i & 4095;
        int e = g_idx[t * 2 + k];
        ev[j] = e;
        if (e < 4) lo += 1ull << (16 * e); else hi += 1ull << (16 * (e - 4));
    }
    sl[0][tid] = lo; sh[0][tid] = hi;
    __syncthreads();
    int buf = 0;
    for (int off = 1; off < 1024; off <<= 1) {
        unsigned long long nl = sl[buf][tid], nh = sh[buf][tid];
        if (tid >= off) { nl += sl[buf][tid - off]; nh += sh[buf][tid - off]; }
        sl[buf ^ 1][tid] = nl; sh[buf ^ 1][tid] = nh;
        buf ^= 1;
        __syncthreads();
    }
    unsigned long long exl = sl[buf][tid] - lo;
    unsigned long long exh = sh[buf][tid] - hi;
    int base[8];
#pragma unroll
    for (int e = 0; e < 4; e++) base[e]     = (int)((exl >> (16 * e)) & 0xFFFF);
#pragma unroll
    for (int e = 0; e < 4; e++) base[4 + e] = (int)((exh >> (16 * e)) & 0xFFFF);
#pragma unroll
    for (int j = 0; j < 8; j++) {
        int i = tid * 8 + j;
        int k = i >> 12;
        int t = i & 4095;
        int e = ev[j];
        int loc = base[e]++;
        if (loc < CAP) {
            g_slot_tok[e * CAP + loc] = t;
            g_slot_w[e * CAP + loc]   = g_gate[t * 2 + k];
        }
    }
}

// ---- shared MMA fragment compute over one resident K-tile (BK=32) ----
__device__ __forceinline__ void tile_mma(const float* __restrict__ As,
                                         const float* __restrict__ Bs,
                                         int wm, int wn, int g, int tg,
                                         float acc[4][4][4]) {
#pragma unroll
    for (int ks = 0; ks < 4; ks++) {
        const int kk = ks * 8;
        unsigned a[4][4], bb[4][2];
#pragma unroll
        for (int mf = 0; mf < 4; mf++) {
            int mr = wm + mf * 16;
            a[mf][0] = tf32u(As[(mr + g) * AS_LD + kk + tg]);
            a[mf][1] = tf32u(As[(mr + g + 8) * AS_LD + kk + tg]);
            a[mf][2] = tf32u(As[(mr + g) * AS_LD + kk + tg + 4]);
            a[mf][3] = tf32u(As[(mr + g + 8) * AS_LD + kk + tg + 4]);
        }
#pragma unroll
        for (int nf = 0; nf < 4; nf++) {
            int nc = wn + nf * 8 + g;
            bb[nf][0] = tf32u(Bs[(kk + tg) * BS_LD + nc]);
            bb[nf][1] = tf32u(Bs[(kk + tg + 4) * BS_LD + nc]);
        }
#pragma unroll
        for (int mf = 0; mf < 4; mf++)
#pragma unroll
            for (int nf = 0; nf < 4; nf++)
                mma8(acc[mf][nf], a[mf], bb[nf]);
    }
}

// ---------------- GEMM1: h = relu(gather(x) @ w1 + b1), cp.async 2-stage ----------------
__global__ __launch_bounds__(256, 2)
void gemm1_kernel(const float* __restrict__ x, const float* __restrict__ w1,
                  const float* __restrict__ b1) {
    extern __shared__ float smem[];
    __shared__ int tokS[128];
    const int e  = blockIdx.z;
    const int m0 = blockIdx.y * 128;
    const int n0 = blockIdx.x * 128;
    const int tid = threadIdx.x;
    if (tid < 128) tokS[tid] = g_slot_tok[e * CAP + m0 + tid];
    __syncthreads();

    const float* w1e = w1 + (size_t)e * DMODEL * HID;
    const int warp = tid >> 5, lane = tid & 31;
    const int wm = (warp >> 2) * 64, wn = (warp & 3) * 32;
    const int g = lane >> 2, tg = lane & 3;

    // per-thread persistent load descriptors (K-independent parts)
    const float* aSrc[4]; unsigned aSz[4]; unsigned aDst[4];
    const float* bSrc[4]; unsigned bDst[4];
    unsigned sbase = (unsigned)__cvta_generic_to_shared(smem);
#pragma unroll
    for (int r = 0; r < 4; r++) {
        int idx = tid + 256 * r;
        int m = idx >> 3, kq = idx & 7;
        int tok = tokS[m];
        aSrc[r] = (tok >= 0) ? (x + (size_t)tok * DMODEL + kq * 4) : x;
        aSz[r]  = (tok >= 0) ? 16u : 0u;
        aDst[r] = sbase + (m * AS_LD + kq * 4) * 4;
        int row = idx >> 5, c4 = idx & 31;
        bSrc[r] = w1e + (size_t)row * HID + n0 + c4 * 4;
        bDst[r] = sbase + (AS_SZ + row * BS_LD + c4 * 4) * 4;
    }

    float acc[4][4][4];
#pragma unroll
    for (int mf = 0; mf < 4; mf++)
#pragma unroll
        for (int nf = 0; nf < 4; nf++)
#pragma unroll
            for (int i = 0; i < 4; i++) acc[mf][nf][i] = 0.f;

    const unsigned stB = STAGE_F * 4;      // stage stride in bytes
    // prologue: stage 0
#pragma unroll
    for (int r = 0; r < 4; r++) {
        cp16z(aDst[r], aSrc[r], aSz[r]);
        cp16(bDst[r], bSrc[r]);
    }
    cp_commit();

    const int NK = DMODEL / 32;
    for (int i = 0; i < NK; i++) {
        if (i + 1 < NK) {
            unsigned so = ((i + 1) & 1) * stB;
            int ko = (i + 1) * 32;
#pragma unroll
            for (int r = 0; r < 4; r++) {
                cp16z(aDst[r] + so, aSrc[r] + ko, aSz[r]);
                cp16(bDst[r] + so, bSrc[r] + (size_t)ko * HID);
            }
            cp_commit();
            asm volatile("cp.async.wait_group 1;\n");
        } else {
            asm volatile("cp.async.wait_group 0;\n");
        }
        __syncthreads();
        const float* As = smem + (i & 1) * STAGE_F;
        const float* Bs = As + AS_SZ;
        tile_mma(As, Bs, wm, wn, g, tg, acc);
        __syncthreads();
    }

    float* he = g_h + (size_t)e * CAP * HID;
    const float* b1e = b1 + e * HID;
#pragma unroll
    for (int mf = 0; mf < 4; mf++) {
        int r0 = m0 + wm + mf * 16 + g;
#pragma unroll
        for (int nf = 0; nf < 4; nf++) {
            int c0 = n0 + wn + nf * 8 + 2 * tg;
            float bv0 = b1e[c0], bv1 = b1e[c0 + 1];
            float2 v01 = make_float2(fmaxf(acc[mf][nf][0] + bv0, 0.f),
                                     fmaxf(acc[mf][nf][1] + bv1, 0.f));
            float2 v23 = make_float2(fmaxf(acc[mf][nf][2] + bv0, 0.f),
                                     fmaxf(acc[mf][nf][3] + bv1, 0.f));
            *(float2*)(he + (size_t)r0 * HID + c0)       = v01;
            *(float2*)(he + (size_t)(r0 + 8) * HID + c0) = v23;
        }
    }
}

// ---------------- GEMM2: out = h @ w2 + b2, fused gated scatter, cp.async 2-stage ----------------
__global__ __launch_bounds__(256, 2)
void gemm2_kernel(const float* __restrict__ w2, const float* __restrict__ b2,
                  float* __restrict__ y) {
    extern __shared__ float smem[];
    const int e  = blockIdx.z;
    const int m0 = blockIdx.y * 128;
    const int n0 = blockIdx.x * 128;
    const int tid = threadIdx.x;
    const float* he  = g_h + (size_t)e * CAP * HID;
    const float* w2e = w2 + (size_t)e * HID * DMODEL;
    const int warp = tid >> 5, lane = tid & 31;
    const int wm = (warp >> 2) * 64, wn = (warp & 3) * 32;
    const int g = lane >> 2, tg = lane & 3;

    const float* aSrc[4]; unsigned aDst[4];
    const float* bSrc[4]; unsigned bDst[4];
    unsigned sbase = (unsigned)__cvta_generic_to_shared(smem);
#pragma unroll
    for (int r = 0; r < 4; r++) {
        int idx = tid + 256 * r;
        int m = idx >> 3, kq = idx & 7;
        aSrc[r] = he + (size_t)(m0 + m) * HID + kq * 4;
        aDst[r] = sbase + (m * AS_LD + kq * 4) * 4;
        int row = idx >> 5, c4 = idx & 31;
        bSrc[r] = w2e + (size_t)row * DMODEL + n0 + c4 * 4;
        bDst[r] = sbase + (AS_SZ + row * BS_LD + c4 * 4) * 4;
    }

    float acc[4][4][4];
#pragma unroll
    for (int mf = 0; mf < 4; mf++)
#pragma unroll
        for (int nf = 0; nf < 4; nf++)
#pragma unroll
            for (int i = 0; i < 4; i++) acc[mf][nf][i] = 0.f;

    const unsigned stB = STAGE_F * 4;
#pragma unroll
    for (int r = 0; r < 4; r++) {
        cp16(aDst[r], aSrc[r]);
        cp16(bDst[r], bSrc[r]);
    }
    cp_commit();

    const int NK = HID / 32;
    for (int i = 0; i < NK; i++) {
        if (i + 1 < NK) {
            unsigned so = ((i + 1) & 1) * stB;
            int ko = (i + 1) * 32;
#pragma unroll
            for (int r = 0; r < 4; r++) {
                cp16(aDst[r] + so, aSrc[r] + ko);
                cp16(bDst[r] + so, bSrc[r] + (size_t)ko * DMODEL);
            }
            cp_commit();
            asm volatile("cp.async.wait_group 1;\n");
        } else {
            asm volatile("cp.async.wait_group 0;\n");
        }
        __syncthreads();
        const float* As = smem + (i & 1) * STAGE_F;
        const float* Bs = As + AS_SZ;
        tile_mma(As, Bs, wm, wn, g, tg, acc);
        __syncthreads();
    }

    const float* b2e = b2 + e * DMODEL;
#pragma unroll
    for (int mf = 0; mf < 4; mf++) {
        int r0 = m0 + wm + mf * 16 + g;
        int tokA = g_slot_tok[e * CAP + r0];
        float wA = g_slot_w[e * CAP + r0];
        int tokB = g_slot_tok[e * CAP + r0 + 8];
        float wB = g_slot_w[e * CAP + r0 + 8];
#pragma unroll
        for (int nf = 0; nf < 4; nf++) {
            int c0 = n0 + wn + nf * 8 + 2 * tg;
            float bv0 = b2e[c0], bv1 = b2e[c0 + 1];
            if (tokA >= 0) {
                atomicAdd(y + (size_t)tokA * DMODEL + c0,     wA * (acc[mf][nf][0] + bv0));
                atomicAdd(y + (size_t)tokA * DMODEL + c0 + 1, wA * (acc[mf][nf][1] + bv1));
            }
            if (tokB >= 0) {
                atomicAdd(y + (size_t)tokB * DMODEL + c0,     wB * (acc[mf][nf][2] + bv0));
                atomicAdd(y + (size_t)tokB * DMODEL + c0 + 1, wB * (acc[mf][nf][3] + bv1));
            }
        }
    }
}

// ---------------- launcher ----------------
extern "C" void kernel_launch(void* const* d_in, const int* in_sizes, int n_in,
                              void* d_out, int out_size) {
    (void)in_sizes; (void)n_in; (void)out_size;
    const float* x  = (const float*)d_in[0];
    const float* wg = (const float*)d_in[1];
    const float* w1 = (const float*)d_in[2];
    const float* b1 = (const float*)d_in[3];
    const float* w2 = (const float*)d_in[4];
    const float* b2 = (const float*)d_in[5];
    float* y = (float*)d_out;

    cudaFuncSetAttribute(gemm1_kernel, cudaFuncAttributeMaxDynamicSharedMemorySize, SMEM_BYTES);
    cudaFuncSetAttribute(gemm2_kernel, cudaFuncAttributeMaxDynamicSharedMemorySize, SMEM_BYTES);

    gating_kernel<<<TOKENS / 8, 256>>>(x, wg, y);
    scan_kernel<<<1, 1024>>>();
    gemm1_kernel<<<dim3(HID / 128, CAP / 128, NEXP), 256, SMEM_BYTES>>>(x, w1, b1);
    gemm2_kernel<<<dim3(DMODEL / 128, CAP / 128, NEXP), 256, SMEM_BYTES>>>(w2, b2, y);
}

// round 9
// speedup vs baseline: 1.0853x; 1.0303x over previous
#include <cuda_runtime.h>
#include <cstdint>

#define TOKENS 4096
#define DMODEL 1024
#define NEXP   8
#define TOPK   2
#define HID    4096
#define CAP    1024

// smem tile geometry (floats)
#define AS_LD   36
#define BS_LDN  36
#define AS_SZ   (128 * AS_LD)           // 4608 floats
#define BS_SZ   (128 * BS_LDN)          // 4608 floats
#define STAGE_F (AS_SZ + BS_SZ)         // 9216 floats per stage
#define SMEM_BYTES (2 * STAGE_F * 4)    // 73728 B, 2 stages

// ---------------- device scratch (no allocations allowed) ----------------
__device__ int   g_idx[TOKENS * TOPK];
__device__ float g_gate[TOKENS * TOPK];
__device__ int   g_slot_tok[NEXP * CAP];
__device__ float g_slot_w[NEXP * CAP];
__device__ float g_h[(size_t)NEXP * CAP * HID];            // 134 MB hidden (tf32-rounded)
__device__ float g_xt[(size_t)TOKENS * DMODEL];            // 16.8 MB x (tf32-rounded)
__device__ float g_w1t[(size_t)NEXP * HID * DMODEL];       // 134 MB w1^T [e][h][d] tf32
__device__ float g_w2t[(size_t)NEXP * DMODEL * HID];       // 134 MB w2^T [e][d][h] tf32

// ---------------- helpers ----------------
__device__ __forceinline__ unsigned tf32u(float x) {
    unsigned u;
    asm("cvt.rna.tf32.f32 %0, %1;" : "=r"(u) : "f"(x));
    return u;
}
__device__ __forceinline__ float tf32f(float x) { return __uint_as_float(tf32u(x)); }

__device__ __forceinline__ void mma8(float c[4], const unsigned a[4], const unsigned b[2]) {
    asm volatile(
        "mma.sync.aligned.m16n8k8.row.col.f32.tf32.tf32.f32 "
        "{%0,%1,%2,%3}, {%4,%5,%6,%7}, {%8,%9}, {%0,%1,%2,%3};\n"
        : "+f"(c[0]), "+f"(c[1]), "+f"(c[2]), "+f"(c[3])
        : "r"(a[0]), "r"(a[1]), "r"(a[2]), "r"(a[3]), "r"(b[0]), "r"(b[1]));
}
__device__ __forceinline__ void ldsm4(unsigned& r0, unsigned& r1, unsigned& r2, unsigned& r3,
                                      unsigned addr) {
    asm volatile("ldmatrix.sync.aligned.m8n8.x4.shared.b16 {%0,%1,%2,%3}, [%4];\n"
                 : "=r"(r0), "=r"(r1), "=r"(r2), "=r"(r3) : "r"(addr));
}
__device__ __forceinline__ void cp16(unsigned saddr, const void* g) {
    asm volatile("cp.async.cg.shared.global [%0], [%1], 16;\n" :: "r"(saddr), "l"(g));
}
__device__ __forceinline__ void cp16z(unsigned saddr, const void* g, unsigned sz) {
    asm volatile("cp.async.cg.shared.global [%0], [%1], 16, %2;\n" :: "r"(saddr), "l"(g), "r"(sz));
}
__device__ __forceinline__ void cp_commit() { asm volatile("cp.async.commit_group;\n"); }

// ---------------- gating: logits -> top2 -> renormalized gates ----------------
__global__ void gating_kernel(const float* __restrict__ x, const float* __restrict__ wg,
                              float* __restrict__ y) {
    int gt = blockIdx.x * blockDim.x + threadIdx.x;
    float4 z4 = make_float4(0.f, 0.f, 0.f, 0.f);
#pragma unroll
    for (int i = 0; i < 8; i++)
        ((float4*)y)[gt + i * 131072] = z4;

    int warp = threadIdx.x >> 5, lane = threadIdx.x & 31;
    int t = blockIdx.x * 8 + warp;
    const float4* xr = (const float4*)(x + (size_t)t * DMODEL);
    float lg[8] = {0.f, 0.f, 0.f, 0.f, 0.f, 0.f, 0.f, 0.f};
#pragma unroll
    for (int j = 0; j < 8; j++) {
        int d4 = lane + 32 * j;
        float4 v = xr[d4];
        const float4* wr = (const float4*)(wg + d4 * 4 * NEXP);
        float xv[4] = {v.x, v.y, v.z, v.w};
#pragma unroll
        for (int r = 0; r < 4; r++) {
            float4 w0 = wr[2 * r], w1v = wr[2 * r + 1];
            lg[0] += xv[r] * w0.x;  lg[1] += xv[r] * w0.y;
            lg[2] += xv[r] * w0.z;  lg[3] += xv[r] * w0.w;
            lg[4] += xv[r] * w1v.x; lg[5] += xv[r] * w1v.y;
            lg[6] += xv[r] * w1v.z; lg[7] += xv[r] * w1v.w;
        }
    }
#pragma unroll
    for (int e = 0; e < 8; e++) {
#pragma unroll
        for (int off = 16; off; off >>= 1)
            lg[e] += __shfl_xor_sync(0xffffffffu, lg[e], off);
    }
    if (lane == 0) {
        int e1 = 0; float l1 = lg[0];
        for (int e = 1; e < 8; e++) if (lg[e] > l1) { l1 = lg[e]; e1 = e; }
        int e2 = (e1 == 0) ? 1 : 0; float l2 = lg[e2];
        for (int e = 0; e < 8; e++) if (e != e1 && lg[e] > l2) { l2 = lg[e]; e2 = e; }
        float gg = 1.f / (1.f + expf(l2 - l1));
        g_idx[t * 2] = e1;  g_idx[t * 2 + 1] = e2;
        g_gate[t * 2] = gg; g_gate[t * 2 + 1] = 1.f - gg;
    }
}

// ---------------- GShard slot-major assignment scan ----------------
__global__ void scan_kernel() {
    __shared__ unsigned long long sl[2][1024];
    __shared__ unsigned long long sh[2][1024];
    int tid = threadIdx.x;
    for (int i = tid; i < NEXP * CAP; i += 1024) { g_slot_tok[i] = -1; g_slot_w[i] = 0.f; }

    int ev[8];
    unsigned long long lo = 0ull, hi = 0ull;
#pragma unroll
    for (int j = 0; j < 8; j++) {
        int i = tid * 8 + j;
        int k = i >> 12;
        int t = i & 4095;
        int e = g_idx[t * 2 + k];
        ev[j] = e;
        if (e < 4) lo += 1ull << (16 * e); else hi += 1ull << (16 * (e - 4));
    }
    sl[0][tid] = lo; sh[0][tid] = hi;
    __syncthreads();
    int buf = 0;
    for (int off = 1; off < 1024; off <<= 1) {
        unsigned long long nl = sl[buf][tid], nh = sh[buf][tid];
        if (tid >= off) { nl += sl[buf][tid - off]; nh += sh[buf][tid - off]; }
        sl[buf ^ 1][tid] = nl; sh[buf ^ 1][tid] = nh;
        buf ^= 1;
        __syncthreads();
    }
    unsigned long long exl = sl[buf][tid] - lo;
    unsigned long long exh = sh[buf][tid] - hi;
    int base[8];
#pragma unroll
    for (int e = 0; e < 4; e++) base[e]     = (int)((exl >> (16 * e)) & 0xFFFF);
#pragma unroll
    for (int e = 0; e < 4; e++) base[4 + e] = (int)((exh >> (16 * e)) & 0xFFFF);
#pragma unroll
    for (int j = 0; j < 8; j++) {
        int i = tid * 8 + j;
        int k = i >> 12;
        int t = i & 4095;
        int e = ev[j];
        int loc = base[e]++;
        if (loc < CAP) {
            g_slot_tok[e * CAP + loc] = t;
            g_slot_w[e * CAP + loc]   = g_gate[t * 2 + k];
        }
    }
}

// ---------------- preconvert: round x to tf32 ----------------
__global__ void round_x_kernel(const float* __restrict__ x) {
    int i = blockIdx.x * blockDim.x + threadIdx.x;
    float4 v = ((const float4*)x)[i];
    v.x = tf32f(v.x); v.y = tf32f(v.y); v.z = tf32f(v.z); v.w = tf32f(v.w);
    ((float4*)g_xt)[i] = v;
}

// ---------------- preconvert: transpose + round weights ----------------
// in[e]: R x C row-major  ->  (which ? g_w2t : g_w1t)[e]: C x R row-major, tf32-rounded.
// NOTE: output selected IN DEVICE CODE — passing a __device__ symbol as a host-side
// kernel argument gives the host shadow address (this was the round-8 bug).
__global__ void transpose_w_kernel(const float* __restrict__ in, int R, int C, int which) {
    __shared__ float ts[32][33];
    float* out = which ? g_w2t : g_w1t;
    const float* ine = in + (size_t)blockIdx.z * R * C;
    float* oute = out + (size_t)blockIdx.z * R * C;
    int c0 = blockIdx.x * 32, r0 = blockIdx.y * 32;
    int tx = threadIdx.x, ty = threadIdx.y;
#pragma unroll
    for (int j = 0; j < 32; j += 8)
        ts[ty + j][tx] = ine[(size_t)(r0 + ty + j) * C + c0 + tx];
    __syncthreads();
#pragma unroll
    for (int j = 0; j < 32; j += 8)
        oute[(size_t)(c0 + ty + j) * R + r0 + tx] = tf32f(ts[tx][ty + j]);
}

// ---- MMA over one resident K-tile (BK=32) via ldmatrix, data pre-rounded ----
__device__ __forceinline__ void tile_mma(unsigned AsU, unsigned BsU,
                                         unsigned aOff, unsigned bOff,
                                         float acc[4][4][4]) {
#pragma unroll
    for (int ks = 0; ks < 4; ks++) {
        const unsigned ko = ks * 32;   // 8 tf32 = 32 bytes per mma K-step
        unsigned a[4][4], bb[4][2];
#pragma unroll
        for (int mf = 0; mf < 4; mf++)
            ldsm4(a[mf][0], a[mf][1], a[mf][2], a[mf][3],
                  AsU + aOff + mf * (16 * AS_LD * 4) + ko);
#pragma unroll
        for (int p = 0; p < 2; p++)
            ldsm4(bb[2 * p][0], bb[2 * p][1], bb[2 * p + 1][0], bb[2 * p + 1][1],
                  BsU + bOff + p * (16 * BS_LDN * 4) + ko);
#pragma unroll
        for (int mf = 0; mf < 4; mf++)
#pragma unroll
            for (int nf = 0; nf < 4; nf++)
                mma8(acc[mf][nf], a[mf], bb[nf]);
    }
}

// ---------------- GEMM1: h = relu(gather(xt) @ w1t^T + b1) ----------------
// grid (HID/128, CAP/128, E), 256 thr, 2-stage cp.async, ldmatrix frags
__global__ __launch_bounds__(256, 2)
void gemm1_kernel(const float* __restrict__ b1) {
    extern __shared__ float smem[];
    __shared__ int tokS[128];
    const int e  = blockIdx.z;
    const int m0 = blockIdx.y * 128;
    const int n0 = blockIdx.x * 128;
    const int tid = threadIdx.x;
    if (tid < 128) tokS[tid] = g_slot_tok[e * CAP + m0 + tid];
    __syncthreads();

    const float* w1te = g_w1t + (size_t)e * HID * DMODEL;   // [h][d], n-major
    const int warp = tid >> 5, lane = tid & 31;
    const int wm = (warp >> 2) * 64, wn = (warp & 3) * 32;
    const int g = lane >> 2, tg = lane & 3;

    const float* aSrc[4]; unsigned aSz[4]; unsigned aDst[4];
    const float* bSrc[4]; unsigned bDst[4];
    unsigned sbase = (unsigned)__cvta_generic_to_shared(smem);
#pragma unroll
    for (int r = 0; r < 4; r++) {
        int idx = tid + 256 * r;
        int row = idx >> 3, kq = idx & 7;
        int tok = tokS[row];
        aSrc[r] = (tok >= 0) ? (g_xt + (size_t)tok * DMODEL + kq * 4) : g_xt;
        aSz[r]  = (tok >= 0) ? 16u : 0u;
        aDst[r] = sbase + (row * AS_LD + kq * 4) * 4;
        bSrc[r] = w1te + (size_t)(n0 + row) * DMODEL + kq * 4;
        bDst[r] = sbase + (AS_SZ + row * BS_LDN + kq * 4) * 4;
    }

    // ldmatrix per-lane offsets
    const int t8 = lane >> 3, lr = lane & 7;
    const unsigned aOff = ((wm + ((t8 & 1) << 3) + lr) * AS_LD + ((t8 >> 1) << 2)) * 4;
    const unsigned bOff = (AS_SZ + (wn + ((t8 >> 1) << 3) + lr) * BS_LDN + ((t8 & 1) << 2)) * 4;

    float acc[4][4][4];
#pragma unroll
    for (int mf = 0; mf < 4; mf++)
#pragma unroll
        for (int nf = 0; nf < 4; nf++)
#pragma unroll
            for (int i = 0; i < 4; i++) acc[mf][nf][i] = 0.f;

    const unsigned stB = STAGE_F * 4;
#pragma unroll
    for (int r = 0; r < 4; r++) { cp16z(aDst[r], aSrc[r], aSz[r]); cp16(bDst[r], bSrc[r]); }
    cp_commit();

    const int NK = DMODEL / 32;
    for (int i = 0; i < NK; i++) {
        asm volatile("cp.async.wait_group 0;\n");
        __syncthreads();
        if (i + 1 < NK) {
            unsigned so = ((i + 1) & 1) * stB;
            int ko = (i + 1) * 32;
#pragma unroll
            for (int r = 0; r < 4; r++) {
                cp16z(aDst[r] + so, aSrc[r] + ko, aSz[r]);
                cp16(bDst[r] + so, bSrc[r] + ko);
            }
            cp_commit();
        }
        unsigned su = sbase + (i & 1) * stB;
        tile_mma(su, su, aOff, bOff, acc);
    }

    float* he = g_h + (size_t)e * CAP * HID;
    const float* b1e = b1 + e * HID;
#pragma unroll
    for (int mf = 0; mf < 4; mf++) {
        int r0 = m0 + wm + mf * 16 + g;
#pragma unroll
        for (int nf = 0; nf < 4; nf++) {
            int c0 = n0 + wn + nf * 8 + 2 * tg;
            float bv0 = b1e[c0], bv1 = b1e[c0 + 1];
            float2 v01 = make_float2(tf32f(fmaxf(acc[mf][nf][0] + bv0, 0.f)),
                                     tf32f(fmaxf(acc[mf][nf][1] + bv1, 0.f)));
            float2 v23 = make_float2(tf32f(fmaxf(acc[mf][nf][2] + bv0, 0.f)),
                                     tf32f(fmaxf(acc[mf][nf][3] + bv1, 0.f)));
            *(float2*)(he + (size_t)r0 * HID + c0)       = v01;
            *(float2*)(he + (size_t)(r0 + 8) * HID + c0) = v23;
        }
    }
}

// ---------------- GEMM2: y += gate * (h @ w2t^T + b2), fused scatter ----------------
// grid (DMODEL/128, CAP/128, E)
__global__ __launch_bounds__(256, 2)
void gemm2_kernel(const float* __restrict__ b2, float* __restrict__ y) {
    extern __shared__ float smem[];
    const int e  = blockIdx.z;
    const int m0 = blockIdx.y * 128;
    const int n0 = blockIdx.x * 128;
    const int tid = threadIdx.x;
    const float* he   = g_h + (size_t)e * CAP * HID;
    const float* w2te = g_w2t + (size_t)e * DMODEL * HID;   // [d][h], n-major
    const int warp = tid >> 5, lane = tid & 31;
    const int wm = (warp >> 2) * 64, wn = (warp & 3) * 32;
    const int g = lane >> 2, tg = lane & 3;

    const float* aSrc[4]; unsigned aDst[4];
    const float* bSrc[4]; unsigned bDst[4];
    unsigned sbase = (unsigned)__cvta_generic_to_shared(smem);
#pragma unroll
    for (int r = 0; r < 4; r++) {
        int idx = tid + 256 * r;
        int row = idx >> 3, kq = idx & 7;
        aSrc[r] = he + (size_t)(m0 + row) * HID + kq * 4;
        aDst[r] = sbase + (row * AS_LD + kq * 4) * 4;
        bSrc[r] = w2te + (size_t)(n0 + row) * HID + kq * 4;
        bDst[r] = sbase + (AS_SZ + row * BS_LDN + kq * 4) * 4;
    }

    const int t8 = lane >> 3, lr = lane & 7;
    const unsigned aOff = ((wm + ((t8 & 1) << 3) + lr) * AS_LD + ((t8 >> 1) << 2)) * 4;
    const unsigned bOff = (AS_SZ + (wn + ((t8 >> 1) << 3) + lr) * BS_LDN + ((t8 & 1) << 2)) * 4;

    float acc[4][4][4];
#pragma unroll
    for (int mf = 0; mf < 4; mf++)
#pragma unroll
        for (int nf = 0; nf < 4; nf++)
#pragma unroll
            for (int i = 0; i < 4; i++) acc[mf][nf][i] = 0.f;

    const unsigned stB = STAGE_F * 4;
#pragma unroll
    for (int r = 0; r < 4; r++) { cp16(aDst[r], aSrc[r]); cp16(bDst[r], bSrc[r]); }
    cp_commit();

    const int NK = HID / 32;
    for (int i = 0; i < NK; i++) {
        asm volatile("cp.async.wait_group 0;\n");
        __syncthreads();
        if (i + 1 < NK) {
            unsigned so = ((i + 1) & 1) * stB;
            int ko = (i + 1) * 32;
#pragma unroll
            for (int r = 0; r < 4; r++) {
                cp16(aDst[r] + so, aSrc[r] + ko);
                cp16(bDst[r] + so, bSrc[r] + ko);
            }
            cp_commit();
        }
        unsigned su = sbase + (i & 1) * stB;
        tile_mma(su, su, aOff, bOff, acc);
    }

    const float* b2e = b2 + e * DMODEL;
#pragma unroll
    for (int mf = 0; mf < 4; mf++) {
        int r0 = m0 + wm + mf * 16 + g;
        int tokA = g_slot_tok[e * CAP + r0];
        float wA = g_slot_w[e * CAP + r0];
        int tokB = g_slot_tok[e * CAP + r0 + 8];
        float wB = g_slot_w[e * CAP + r0 + 8];
#pragma unroll
        for (int nf = 0; nf < 4; nf++) {
            int c0 = n0 + wn + nf * 8 + 2 * tg;
            float bv0 = b2e[c0], bv1 = b2e[c0 + 1];
            if (tokA >= 0) {
                atomicAdd(y + (size_t)tokA * DMODEL + c0,     wA * (acc[mf][nf][0] + bv0));
                atomicAdd(y + (size_t)tokA * DMODEL + c0 + 1, wA * (acc[mf][nf][1] + bv1));
            }
            if (tokB >= 0) {
                atomicAdd(y + (size_t)tokB * DMODEL + c0,     wB * (acc[mf][nf][2] + bv0));
                atomicAdd(y + (size_t)tokB * DMODEL + c0 + 1, wB * (acc[mf][nf][3] + bv1));
            }
        }
    }
}

// ---------------- launcher ----------------
extern "C" void kernel_launch(void* const* d_in, const int* in_sizes, int n_in,
                              void* d_out, int out_size) {
    (void)in_sizes; (void)n_in; (void)out_size;
    const float* x  = (const float*)d_in[0];
    const float* wg = (const float*)d_in[1];
    const float* w1 = (const float*)d_in[2];
    const float* b1 = (const float*)d_in[3];
    const float* w2 = (const float*)d_in[4];
    const float* b2 = (const float*)d_in[5];
    float* y = (float*)d_out;

    cudaFuncSetAttribute(gemm1_kernel, cudaFuncAttributeMaxDynamicSharedMemorySize, SMEM_BYTES);
    cudaFuncSetAttribute(gemm2_kernel, cudaFuncAttributeMaxDynamicSharedMemorySize, SMEM_BYTES);

    gating_kernel<<<TOKENS / 8, 256>>>(x, wg, y);
    scan_kernel<<<1, 1024>>>();
    round_x_kernel<<<(TOKENS * DMODEL / 4) / 256, 256>>>(x);
    transpose_w_kernel<<<dim3(HID / 32, DMODEL / 32, NEXP), dim3(32, 8)>>>(w1, DMODEL, HID, 0);
    transpose_w_kernel<<<dim3(DMODEL / 32, HID / 32, NEXP), dim3(32, 8)>>>(w2, HID, DMODEL, 1);
    gemm1_kernel<<<dim3(HID / 128, CAP / 128, NEXP), 256, SMEM_BYTES>>>(b1);
    gemm2_kernel<<<dim3(DMODEL / 128, CAP / 128, NEXP), 256, SMEM_BYTES>>>(b2, y);
}